// round 15
// baseline (speedup 1.0000x reference)
#include <cuda_runtime.h>
#include <cuda_bf16.h>
#include <cstdint>

#define N_NODES 100000
#define N_EDGES 1600000
#define NF      64
#define NG      1024
#define NB      2048
#define NBLK    ((N_NODES + 1023) / 1024)   // 98 scan blocks

// ---------------- scratch (static device globals; no allocation) ----------------
__device__ int   g_deg[N_NODES];
__device__ __align__(16) float g_dinv[N_NODES];
__device__ int   g_rowoff[N_NODES];          // row begin (end = beg + deg)
__device__ int   g_cursor[N_NODES];
__device__ int   g_scan_total;
__device__ __align__(16) int2  g_csr[N_EDGES];               // (src, w as bf16x2 bits)
__device__ __align__(16) __nv_bfloat162 g_xb [N_NODES * 32];  // x in bf16
__device__ __align__(16) __nv_bfloat162 g_h1b[N_NODES * 32];
__device__ __align__(16) __nv_bfloat162 g_h2b[N_NODES * 32];
__device__ __align__(16) float g_pool[NG * NF];
__device__ int   g_cnt[NG];

__device__ __forceinline__ int clampi(int v, int hi) {
    return v < 0 ? 0 : (v >= hi ? hi - 1 : v);
}
__device__ __forceinline__ __nv_bfloat162 bf2_from_bits(uint32_t u) {
    return *reinterpret_cast<__nv_bfloat162*>(&u);
}
__device__ __forceinline__ uint32_t bits_from_bf2(__nv_bfloat162 v) {
    return *reinterpret_cast<uint32_t*>(&v);
}

// ---------------- zero + x->bf16 (fused, independent work) ----------------
__global__ void k_zero_xb(const float* __restrict__ x) {
    int i = blockIdx.x * blockDim.x + threadIdx.x;
    int stride = gridDim.x * blockDim.x;
    if (i == 0) g_scan_total = 0;
    for (int j = i; j < N_NODES; j += stride) g_deg[j] = 0;
    for (int j = i; j < NG * NF; j += stride) g_pool[j] = 0.0f;
    for (int j = i; j < NG; j += stride) g_cnt[j] = 0;
    const float2* x2 = (const float2*)x;
    for (int j = i; j < N_NODES * 32; j += stride)
        g_xb[j] = __float22bfloat162_rn(x2[j]);
}

// histogram: in-degree over dst (int4 vectorized)
__global__ void k_hist(const int* __restrict__ ei) {
    int i = blockIdx.x * blockDim.x + threadIdx.x;
    int stride = gridDim.x * blockDim.x;
    const int4* dst4 = (const int4*)(ei + N_EDGES);
    for (int e = i; e < N_EDGES / 4; e += stride) {
        int4 d = dst4[e];
        atomicAdd(&g_deg[clampi(d.x, N_NODES)], 1);
        atomicAdd(&g_deg[clampi(d.y, N_NODES)], 1);
        atomicAdd(&g_deg[clampi(d.z, N_NODES)], 1);
        atomicAdd(&g_deg[clampi(d.w, N_NODES)], 1);
    }
}

// ---------------- single-pass scan: block-local prefix + atomic block offset ----
// CSR row order across blocks is atomic-arrival order (legal: agg only needs
// each node's contiguous [beg, beg+deg) range). Also computes dinv + graph counts.
__global__ __launch_bounds__(1024) void k_scan(const int* __restrict__ batch) {
    __shared__ int ssum[1024];
    __shared__ int s_off;
    int t = threadIdx.x;
    int idx = blockIdx.x * 1024 + t;
    int v = (idx < N_NODES) ? g_deg[idx] : 0;
    ssum[t] = v;
    __syncthreads();
    for (int d = 1; d < 1024; d <<= 1) {
        int u = (t >= d) ? ssum[t - d] : 0;
        __syncthreads();
        ssum[t] += u;
        __syncthreads();
    }
    if (t == 1023) s_off = atomicAdd(&g_scan_total, ssum[1023]);
    __syncthreads();
    if (idx < N_NODES) {
        int beg = s_off + ssum[t] - v;
        g_rowoff[idx] = beg;
        g_cursor[idx] = beg;
        g_dinv[idx] = rsqrtf((float)v + 1.0f);
        atomicAdd(&g_cnt[clampi(batch[idx], NG)], 1);
    }
}

__global__ void k_scatter(const int* __restrict__ ei) {
    int i = blockIdx.x * blockDim.x + threadIdx.x;
    int stride = gridDim.x * blockDim.x;
    const int4* src4 = (const int4*)ei;
    const int4* dst4 = (const int4*)(ei + N_EDGES);
    for (int e = i; e < N_EDGES / 4; e += stride) {
        int4 sv = src4[e];
        int4 dv = dst4[e];
#define SCAT(SS, DD)                                                    \
        {                                                               \
            int s = clampi(SS, N_NODES);                                \
            int d = clampi(DD, N_NODES);                                \
            int pos = atomicAdd(&g_cursor[d], 1);                       \
            __nv_bfloat16 wb = __float2bfloat16(g_dinv[s] * g_dinv[d]); \
            uint32_t wu = (uint32_t)__bfloat16_as_ushort(wb);           \
            g_csr[pos] = make_int2(s, (int)(wu | (wu << 16)));          \
        }
        SCAT(sv.x, dv.x) SCAT(sv.y, dv.y) SCAT(sv.z, dv.z) SCAT(sv.w, dv.w)
#undef SCAT
    }
}

// ---------------- fused layer: agg -> smem -> tensor-core GEMM -> epilogue ----
// block = 256 thr (8 warps) handles 128 nodes.
// Phase 1: each warp aggregates its 16 nodes (4 nodes x 4 chunks; 8 lanes/node,
//          lane owns 16B) directly into the sA tile (bf16, HFMA2 accum).
// Phase 2: mma.m16n8k16 GEMM vs W (staged as W^T in sB), bias.
// mode: 0 = ReLU + bf16 store to h-buffer, 2 = pool atomics epilogue.
__device__ __forceinline__ void mma16816(float& c0, float& c1, float& c2, float& c3,
                                         uint32_t a0, uint32_t a1, uint32_t a2, uint32_t a3,
                                         uint32_t b0, uint32_t b1) {
    asm volatile(
        "mma.sync.aligned.m16n8k16.row.col.f32.bf16.bf16.f32 "
        "{%0,%1,%2,%3}, {%4,%5,%6,%7}, {%8,%9}, {%0,%1,%2,%3};\n"
        : "+f"(c0), "+f"(c1), "+f"(c2), "+f"(c3)
        : "r"(a0), "r"(a1), "r"(a2), "r"(a3), "r"(b0), "r"(b1));
}

__global__ __launch_bounds__(256) void k_layer(const float* __restrict__ W,
                                               const float* __restrict__ b,
                                               const int* __restrict__ batch,
                                               int mode, int src_sel, int dst_sel) {
    __shared__ __nv_bfloat16 sA[128 * 72];   // 128 nodes x 64 feats, pitch 72
    __shared__ __nv_bfloat16 sB[64 * 72];    // W^T: sB[n][k], pitch 72
    __shared__ float sbias[64];
    int tid = threadIdx.x;

    // stage W^T (bf16) and bias
    for (int i = tid; i < 64 * 64; i += 256) {
        int k = i >> 6, n = i & 63;
        sB[n * 72 + k] = __float2bfloat16(W[i]);
    }
    if (tid < 64) sbias[tid] = b[tid];

    // ---- Phase 1: aggregation straight into sA ----
    int node_base = blockIdx.x * 128;
    int warp = tid >> 5, lane = tid & 31;
    int sub = lane >> 3;   // node within 4-node chunk
    int sl  = lane & 7;    // 16B segment within row
    const uint4* hb = (const uint4*)(src_sel == 0 ? g_xb
                                   : (src_sel == 1 ? g_h1b : g_h2b));
#pragma unroll
    for (int c = 0; c < 4; c++) {
        int row = warp * 16 + c * 4 + sub;
        int n = node_base + row;
        uint4 outv = make_uint4(0, 0, 0, 0);
        if (n < N_NODES) {
            float dv = g_dinv[n];
            __nv_bfloat162 sn2 = __float2bfloat162_rn(dv * dv);
            uint4 hv = hb[n * 8 + sl];
            __nv_bfloat162 a0 = __hmul2(sn2, bf2_from_bits(hv.x));
            __nv_bfloat162 a1 = __hmul2(sn2, bf2_from_bits(hv.y));
            __nv_bfloat162 a2 = __hmul2(sn2, bf2_from_bits(hv.z));
            __nv_bfloat162 a3 = __hmul2(sn2, bf2_from_bits(hv.w));
            int beg = g_rowoff[n];
            int end = beg + g_deg[n];
            int j = beg;
            for (; j + 2 <= end; j += 2) {
                int2 e0 = g_csr[j], e1 = g_csr[j + 1];
                uint4 v0 = hb[e0.x * 8 + sl];
                uint4 v1 = hb[e1.x * 8 + sl];
                __nv_bfloat162 w0 = bf2_from_bits((uint32_t)e0.y);
                __nv_bfloat162 w1 = bf2_from_bits((uint32_t)e1.y);
                a0 = __hfma2(w0, bf2_from_bits(v0.x), a0);
                a1 = __hfma2(w0, bf2_from_bits(v0.y), a1);
                a2 = __hfma2(w0, bf2_from_bits(v0.z), a2);
                a3 = __hfma2(w0, bf2_from_bits(v0.w), a3);
                a0 = __hfma2(w1, bf2_from_bits(v1.x), a0);
                a1 = __hfma2(w1, bf2_from_bits(v1.y), a1);
                a2 = __hfma2(w1, bf2_from_bits(v1.z), a2);
                a3 = __hfma2(w1, bf2_from_bits(v1.w), a3);
            }
            if (j < end) {
                int2 e = g_csr[j];
                uint4 v = hb[e.x * 8 + sl];
                __nv_bfloat162 w = bf2_from_bits((uint32_t)e.y);
                a0 = __hfma2(w, bf2_from_bits(v.x), a0);
                a1 = __hfma2(w, bf2_from_bits(v.y), a1);
                a2 = __hfma2(w, bf2_from_bits(v.z), a2);
                a3 = __hfma2(w, bf2_from_bits(v.w), a3);
            }
            outv = make_uint4(bits_from_bf2(a0), bits_from_bf2(a1),
                              bits_from_bf2(a2), bits_from_bf2(a3));
        }
        *(uint4*)(sA + row * 72 + sl * 8) = outv;   // 144B pitch, 16B aligned
    }
    __syncthreads();

    // ---- Phase 2: tensor-core GEMM ----
    int node0 = node_base + warp * 16;
    if (node0 >= N_NODES) return;   // N_NODES % 16 == 0
    int g = lane >> 2, ct = lane & 3;

    float c[8][4];
#pragma unroll
    for (int nt = 0; nt < 8; nt++)
#pragma unroll
        for (int q = 0; q < 4; q++) c[nt][q] = 0.f;

    int r0 = warp * 16 + g;
#pragma unroll
    for (int ks = 0; ks < 4; ks++) {
        const __nv_bfloat16* ab = sA + ks * 16 + ct * 2;
        uint32_t a0 = *(const uint32_t*)(ab + r0 * 72);
        uint32_t a1 = *(const uint32_t*)(ab + (r0 + 8) * 72);
        uint32_t a2 = *(const uint32_t*)(ab + r0 * 72 + 8);
        uint32_t a3 = *(const uint32_t*)(ab + (r0 + 8) * 72 + 8);
#pragma unroll
        for (int nt = 0; nt < 8; nt++) {
            const __nv_bfloat16* bb = sB + (nt * 8 + g) * 72 + ks * 16 + ct * 2;
            uint32_t b0 = *(const uint32_t*)(bb);
            uint32_t b1 = *(const uint32_t*)(bb + 8);
            mma16816(c[nt][0], c[nt][1], c[nt][2], c[nt][3], a0, a1, a2, a3, b0, b1);
        }
    }

    int m0 = node0 + g, m1 = m0 + 8;
    if (mode == 2) {
        int gm0 = clampi(batch[m0], NG);
        int gm1 = clampi(batch[m1], NG);
#pragma unroll
        for (int nt = 0; nt < 8; nt++) {
            int col = nt * 8 + ct * 2;
            float bx = sbias[col], by = sbias[col + 1];
            float v0 = c[nt][0] + bx, v1 = c[nt][1] + by;
            float v2 = c[nt][2] + bx, v3 = c[nt][3] + by;
            if (gm0 == gm1) {
                atomicAdd(&g_pool[gm0 * 64 + col],     v0 + v2);
                atomicAdd(&g_pool[gm0 * 64 + col + 1], v1 + v3);
            } else {
                atomicAdd(&g_pool[gm0 * 64 + col],     v0);
                atomicAdd(&g_pool[gm0 * 64 + col + 1], v1);
                atomicAdd(&g_pool[gm1 * 64 + col],     v2);
                atomicAdd(&g_pool[gm1 * 64 + col + 1], v3);
            }
        }
        return;
    }

    __nv_bfloat162* ob = (dst_sel == 1 ? g_h1b : g_h2b);
#pragma unroll
    for (int nt = 0; nt < 8; nt++) {
        int col = nt * 8 + ct * 2;
        float bx = sbias[col], by = sbias[col + 1];
        float v0 = fmaxf(c[nt][0] + bx, 0.f), v1 = fmaxf(c[nt][1] + by, 0.f);
        float v2 = fmaxf(c[nt][2] + bx, 0.f), v3 = fmaxf(c[nt][3] + by, 0.f);
        ob[m0 * 32 + nt * 4 + ct] = __float22bfloat162_rn(make_float2(v0, v1));
        ob[m1 * 32 + nt * 4 + ct] = __float22bfloat162_rn(make_float2(v2, v3));
    }
}

// ---------------- dense + bias + softmax-threshold (8 graphs/block) ----------------
__global__ __launch_bounds__(256) void k_dense(const float* __restrict__ Wd,
                                               const float* __restrict__ bd,
                                               float* __restrict__ out) {
    __shared__ float sp[8 * 64];
    __shared__ float sred[256];
    int tid = threadIdx.x;
    int g0 = blockIdx.x * 8;

    for (int i = tid; i < 8 * 64; i += 256) {   // mean pool into shared
        int r = i >> 6, f = i & 63;
        int c = g_cnt[g0 + r];
        if (c < 1) c = 1;
        sp[i] = g_pool[(g0 + r) * 64 + f] / (float)c;
    }
    __syncthreads();

    float acc[8][8];
#pragma unroll
    for (int r = 0; r < 8; r++)
#pragma unroll
        for (int j = 0; j < 8; j++) acc[r][j] = 0.f;

    for (int k = 0; k < 64; k++) {
        float w[8];
#pragma unroll
        for (int j = 0; j < 8; j++) w[j] = Wd[k * NB + tid + 256 * j];
#pragma unroll
        for (int r = 0; r < 8; r++) {
            float p = sp[r * 64 + k];
#pragma unroll
            for (int j = 0; j < 8; j++) acc[r][j] += p * w[j];
        }
    }
#pragma unroll
    for (int j = 0; j < 8; j++) {
        float bb = bd[tid + 256 * j];
#pragma unroll
        for (int r = 0; r < 8; r++) acc[r][j] += bb;
    }

    for (int r = 0; r < 8; r++) {
        float m = -3.402823466e38f;
#pragma unroll
        for (int j = 0; j < 8; j++) m = fmaxf(m, acc[r][j]);
        sred[tid] = m;
        __syncthreads();
        for (int s = 128; s > 0; s >>= 1) {
            if (tid < s) sred[tid] = fmaxf(sred[tid], sred[tid + s]);
            __syncthreads();
        }
        float rowmax = sred[0];
        __syncthreads();

        float s = 0.f;
#pragma unroll
        for (int j = 0; j < 8; j++) s += expf(acc[r][j] - rowmax);
        sred[tid] = s;
        __syncthreads();
        for (int st = 128; st > 0; st >>= 1) {
            if (tid < st) sred[tid] += sred[tid + st];
            __syncthreads();
        }
        float thr = 0.5f * sred[0];
        __syncthreads();

#pragma unroll
        for (int j = 0; j < 8; j++) {
            int col = tid + 256 * j;
            out[(size_t)(g0 + r) * NB + col] =
                (expf(acc[r][j] - rowmax) >= thr) ? 1.0f : 0.0f;
        }
    }
}

// ---------------- launch ----------------
extern "C" void kernel_launch(void* const* d_in, const int* in_sizes, int n_in,
                              void* d_out, int out_size) {
    const float* x      = (const float*)d_in[0];
    const int*   ei     = (const int*)d_in[1];     // int32
    const int*   bat    = (const int*)d_in[2];     // int32
    const float* W1 = (const float*)d_in[3];
    const float* b1 = (const float*)d_in[4];
    const float* W2 = (const float*)d_in[5];
    const float* b2 = (const float*)d_in[6];
    const float* W3 = (const float*)d_in[7];
    const float* b3 = (const float*)d_in[8];
    const float* Wd = (const float*)d_in[9];
    const float* bd = (const float*)d_in[10];
    float* out = (float*)d_out;

    const int LAYER_BLOCKS = (N_NODES + 127) / 128;   // 782

    k_zero_xb<<<512, 256>>>(x);
    k_hist<<<1024, 256>>>(ei);
    k_scan<<<NBLK, 1024>>>(bat);
    k_scatter<<<(N_EDGES / 4 + 255) / 256, 256>>>(ei);

    // layer 1: agg(xb)+gemm(+ReLU) -> h1b
    k_layer<<<LAYER_BLOCKS, 256>>>(W1, b1, bat, 0, 0, 1);
    // layer 2: agg(h1b)+gemm(+ReLU) -> h2b
    k_layer<<<LAYER_BLOCKS, 256>>>(W2, b2, bat, 0, 1, 2);
    // layer 3: agg(h2b)+gemm(+pool epilogue)
    k_layer<<<LAYER_BLOCKS, 256>>>(W3, b3, bat, 2, 2, 0);

    // dense/softmax/threshold
    k_dense<<<NG / 8, 256>>>(Wd, bd, out);
}